// round 16
// baseline (speedup 1.0000x reference)
#include <cuda_runtime.h>
#include <cuda_bf16.h>
#include <cuda_fp16.h>
#include <cstdint>
#include <math.h>

#define Bsz   512
#define Nn    256
#define NODES (Bsz * Nn)      // 131072
#define DIN   32
#define HID   128
#define HEADS 4
#define Knn   5
#define DOUT  8
#define CAP   40
#define NEG_SLOPE 0.2f
#define FULLM 0xffffffffu
#define NTILES (NODES / 128)  // 1024

// ---------------- static device scratch ----------------
__device__ int     g_rdeg[NODES];
__device__ uint8_t g_adj8[(size_t)NODES * CAP];     // local (in-batch) indices
__device__ __half  g_hbuf[(size_t)NODES * HID];     // fp16 H (gathered by aggregate)
__device__ float   g_xbuf[(size_t)NODES * HID];
__device__ float   g_als[(size_t)NODES * HEADS];
__device__ float   g_ald[(size_t)NODES * HEADS];
// bf16 hi/lo images of W^T: [n=128 rows][k] row-major
__device__ __nv_bfloat16 g_w1_hi[128 * DIN],  g_w1_lo[128 * DIN];
__device__ __nv_bfloat16 g_w2_hi[128 * HID],  g_w2_lo[128 * HID];
__device__ __nv_bfloat16 g_wm1_hi[128 * HID], g_wm1_lo[128 * HID];

__device__ __forceinline__ float tanh_fast(float x) {
    return __fdividef(2.f, 1.f + __expf(-2.f * x)) - 1.f;
}
__device__ __forceinline__ float lrelu(float v) {
    return (v > 0.f) ? v : NEG_SLOPE * v;
}
__device__ __forceinline__ uint32_t smem_u32(const void* p) {
    uint32_t a;
    asm("{ .reg .u64 t; cvta.to.shared.u64 t, %1; cvt.u32.u64 %0, t; }" : "=r"(a) : "l"(p));
    return a;
}
__device__ __forceinline__ void ldsm_x4(uint32_t* r, uint32_t addr) {
    asm volatile("ldmatrix.sync.aligned.m8n8.x4.shared.b16 {%0,%1,%2,%3}, [%4];"
                 : "=r"(r[0]), "=r"(r[1]), "=r"(r[2]), "=r"(r[3]) : "r"(addr));
}
__device__ __forceinline__ void ldsm_x2(uint32_t* r, uint32_t addr) {
    asm volatile("ldmatrix.sync.aligned.m8n8.x2.shared.b16 {%0,%1}, [%2];"
                 : "=r"(r[0]), "=r"(r[1]) : "r"(addr));
}
__device__ __forceinline__ void mma_bf16(float* c, const uint32_t* a, const uint32_t* b) {
    asm volatile("mma.sync.aligned.m16n8k16.row.col.f32.bf16.bf16.f32 "
                 "{%0,%1,%2,%3}, {%4,%5,%6,%7}, {%8,%9}, {%0,%1,%2,%3};"
                 : "+f"(c[0]), "+f"(c[1]), "+f"(c[2]), "+f"(c[3])
                 : "r"(a[0]), "r"(a[1]), "r"(a[2]), "r"(a[3]), "r"(b[0]), "r"(b[1]));
}
__device__ __forceinline__ uint32_t pack_bf2(__nv_bfloat16 a, __nv_bfloat16 b) {
    return (uint32_t)__bfloat16_as_ushort(a) | ((uint32_t)__bfloat16_as_ushort(b) << 16);
}

// =====================================================================
// Prep: W [K,128] -> hi/lo bf16 images of W^T [128][K]
// =====================================================================
__global__ void prep_w_kernel(const float* __restrict__ W, int K,
                              __nv_bfloat16* __restrict__ hi, __nv_bfloat16* __restrict__ lo)
{
    int idx = blockIdx.x * blockDim.x + threadIdx.x;
    if (idx >= K * 128) return;
    int k = idx >> 7, n = idx & 127;
    float x = W[idx];
    __nv_bfloat16 h = __float2bfloat16(x);
    __nv_bfloat16 l = __float2bfloat16(x - __bfloat162float(h));
    hi[n * K + k] = h;
    lo[n * K + k] = l;
}

// =====================================================================
// KNN v4 (dynamic smem): 1024 threads, 4 threads/node x 64 candidates,
// 4-way merge of sorted top-5 lists (padded to 6 with +inf).
// smem layout: sxy[256]f2 | sdeg[256]i | mbd[6144]f | mbi[6144]i | sadj[10240]u8
// total = 2048 + 1024 + 24576 + 24576 + 10240 = 62464 B
// =====================================================================
#define KNN_SMEM 62464
__global__ __launch_bounds__(1024) void knn_kernel(const float* __restrict__ obs)
{
    extern __shared__ __align__(16) char kdsm[];
    float2*  sxy  = (float2*)kdsm;                        // 2048
    int*     sdeg = (int*)(kdsm + 2048);                  // 1024
    float*   mbd  = (float*)(kdsm + 3072);                // 24576
    int*     mbi  = (int*)(kdsm + 27648);                 // 24576
    uint8_t* sadj = (uint8_t*)(kdsm + 52224);             // 10240

    const int b = blockIdx.x;
    const int t = threadIdx.x;
    const int n = t & (Nn - 1);
    const int q = t >> 8;                          // 0..3

    if (t < Nn) {
        const size_t base = ((size_t)b * Nn + n) * DIN;
        sxy[n] = make_float2(obs[base + 0], obs[base + 1]);
        sdeg[n] = 1;
        sadj[n * CAP + 0] = (uint8_t)n;
    }
    __syncthreads();

    const float2 p = sxy[n];
    float bd[Knn];
    int   bi[Knn];
#pragma unroll
    for (int s = 0; s < Knn; s++) { bd[s] = 3.0e38f; bi[s] = -1; }

    const int j0 = q * 64;
    for (int jj = 0; jj < 64; jj++) {
        const int j = j0 + jj;
        float2 c = sxy[j];
        float dx = c.x - p.x;
        float dy = c.y - p.y;
        float d  = fmaf(dx, dx, dy * dy);
        if (j == n) d = 3.0e38f;
        if (d < bd[Knn - 1]) {
            bd[Knn - 1] = d; bi[Knn - 1] = j;
#pragma unroll
            for (int s = Knn - 2; s >= 0; s--) {
                if (bd[s + 1] < bd[s]) {
                    float td = bd[s]; bd[s] = bd[s + 1]; bd[s + 1] = td;
                    int   ti = bi[s]; bi[s] = bi[s + 1]; bi[s + 1] = ti;
                }
            }
        }
    }
    {
        const int base6 = (n * 4 + q) * (Knn + 1);
#pragma unroll
        for (int s = 0; s < Knn; s++) {
            mbd[base6 + s] = bd[s];
            mbi[base6 + s] = bi[s];
        }
        mbd[base6 + Knn] = 3.0e38f;
        mbi[base6 + Knn] = -1;
    }
    __syncthreads();

    if (t < Nn) {
        int ia0 = 0, ia1 = 0, ia2 = 0, ia3 = 0;
        const int b0 = (n * 4 + 0) * (Knn + 1);
        const int b1 = (n * 4 + 1) * (Knn + 1);
        const int b2 = (n * 4 + 2) * (Knn + 1);
        const int b3 = (n * 4 + 3) * (Knn + 1);
#pragma unroll
        for (int s = 0; s < Knn; s++) {
            float v0 = mbd[b0 + ia0];
            float v1 = mbd[b1 + ia1];
            float v2 = mbd[b2 + ia2];
            float v3 = mbd[b3 + ia3];
            int jn;
            if (v0 <= v1 && v0 <= v2 && v0 <= v3)      { jn = mbi[b0 + ia0]; ia0++; }
            else if (v1 <= v2 && v1 <= v3)             { jn = mbi[b1 + ia1]; ia1++; }
            else if (v2 <= v3)                         { jn = mbi[b2 + ia2]; ia2++; }
            else                                       { jn = mbi[b3 + ia3]; ia3++; }
            int p2 = atomicAdd(&sdeg[jn], 1);
            if (p2 < CAP) sadj[jn * CAP + p2] = (uint8_t)n;
        }
    }
    __syncthreads();

    if (t < Nn) {
        int deg = min(sdeg[n], CAP);
        g_rdeg[b * Nn + n] = deg;
        uint8_t* dst = g_adj8 + (size_t)(b * Nn + n) * CAP;
        const uint32_t* srcw = (const uint32_t*)&sadj[n * CAP];
#pragma unroll
        for (int w = 0; w < CAP / 4; w++)
            ((uint32_t*)dst)[w] = srcw[w];
    }
}

// =====================================================================
// PERSISTENT mma.sync GEMM, 3-tile smem, 2 CTAs/SM (unchanged, measured).
// =====================================================================
template<int KDIM, int MODE>
__global__ __launch_bounds__(256, 2) void mma_gemm(
    const float* __restrict__ X,
    const __nv_bfloat16* __restrict__ gBhi, const __nv_bfloat16* __restrict__ gBlo,
    const float* __restrict__ asrc, const float* __restrict__ adst,
    const float* __restrict__ bias, const float* __restrict__ Wm2,
    const float* __restrict__ bm2,
    __half* __restrict__ H, float* __restrict__ ALS, float* __restrict__ ALD,
    float* __restrict__ OUT)
{
    constexpr int PK = KDIM + 8;
    extern __shared__ __align__(16) char smem[];
    __nv_bfloat16* sAhi = (__nv_bfloat16*)smem;
    __nv_bfloat16* sAlo = sAhi + 128 * PK;
    __nv_bfloat16* sB   = sAlo + 128 * PK;
    float* scr = (float*)(sB + 128 * PK);

    const int t = threadIdx.x, wid = t >> 5, lane = t & 31;

    if (MODE == 0) {
        if (t < 128) { scr[t] = asrc[t]; scr[128 + t] = adst[t]; }
    } else {
        if (t < 128) scr[t] = bias[t];
        for (int e = t; e < 1024; e += 256) scr[128 + e] = Wm2[e];
    }
    __syncthreads();

    const int mbase = (wid & 1) * 64;
    const int nbase = (wid >> 1) * 32;
    const int arow = mbase + (lane & 7) + ((lane >> 3) & 1) * 8;
    const int ak   = (lane >> 4) * 8;
    const int brow = nbase + (lane & 7);
    const int bk   = ((lane >> 3) & 1) * 8;
    const int gr = lane >> 2;
    const int qc = (lane & 3) * 2;

    for (int tile = blockIdx.x; tile < NTILES; tile += gridDim.x) {
        const int r0 = tile * 128;

        for (int idx = t; idx < 128 * (KDIM / 2); idx += 256) {
            int row = idx / (KDIM / 2);
            int k   = (idx % (KDIM / 2)) * 2;
            float2 v = *(const float2*)&X[(size_t)(r0 + row) * KDIM + k];
            __nv_bfloat16 h0 = __float2bfloat16(v.x);
            __nv_bfloat16 h1 = __float2bfloat16(v.y);
            __nv_bfloat16 l0 = __float2bfloat16(v.x - __bfloat162float(h0));
            __nv_bfloat16 l1 = __float2bfloat16(v.y - __bfloat162float(h1));
            *(uint32_t*)&sAhi[row * PK + k] = pack_bf2(h0, h1);
            *(uint32_t*)&sAlo[row * PK + k] = pack_bf2(l0, l1);
        }
        for (int idx = t; idx < 128 * (KDIM / 8); idx += 256) {
            int n  = idx / (KDIM / 8);
            int kc = (idx % (KDIM / 8)) * 8;
            *(float4*)&sB[n * PK + kc] = *(const float4*)&gBhi[n * KDIM + kc];
        }
        __syncthreads();

        float c[4][4][4];
#pragma unroll
        for (int mi = 0; mi < 4; mi++)
#pragma unroll
            for (int ni = 0; ni < 4; ni++)
#pragma unroll
                for (int q = 0; q < 4; q++) c[mi][ni][q] = 0.f;

#pragma unroll
        for (int p = 0; p < 2; p++) {
            const __nv_bfloat16* A = (p == 1) ? sAlo : sAhi;
#pragma unroll
            for (int ks = 0; ks < KDIM / 16; ks++) {
                uint32_t a[4][4], b[4][2];
#pragma unroll
                for (int mi = 0; mi < 4; mi++)
                    ldsm_x4(a[mi], smem_u32(&A[(arow + mi * 16) * PK + ks * 16 + ak]));
#pragma unroll
                for (int ni = 0; ni < 4; ni++)
                    ldsm_x2(b[ni], smem_u32(&sB[(brow + ni * 8) * PK + ks * 16 + bk]));
#pragma unroll
                for (int mi = 0; mi < 4; mi++)
#pragma unroll
                    for (int ni = 0; ni < 4; ni++)
                        mma_bf16(c[mi][ni], a[mi], b[ni]);
            }
        }
        __syncthreads();
        for (int idx = t; idx < 128 * (KDIM / 8); idx += 256) {
            int n  = idx / (KDIM / 8);
            int kc = (idx % (KDIM / 8)) * 8;
            *(float4*)&sB[n * PK + kc] = *(const float4*)&gBlo[n * KDIM + kc];
        }
        __syncthreads();
#pragma unroll
        for (int ks = 0; ks < KDIM / 16; ks++) {
            uint32_t a[4][4], b[4][2];
#pragma unroll
            for (int mi = 0; mi < 4; mi++)
                ldsm_x4(a[mi], smem_u32(&sAhi[(arow + mi * 16) * PK + ks * 16 + ak]));
#pragma unroll
            for (int ni = 0; ni < 4; ni++)
                ldsm_x2(b[ni], smem_u32(&sB[(brow + ni * 8) * PK + ks * 16 + bk]));
#pragma unroll
            for (int mi = 0; mi < 4; mi++)
#pragma unroll
                for (int ni = 0; ni < 4; ni++)
                    mma_bf16(c[mi][ni], a[mi], b[ni]);
        }
        __syncthreads();

        if (MODE == 0) {
            const int head = wid >> 1;
#pragma unroll
            for (int mi = 0; mi < 4; mi++) {
                const int row0 = r0 + mbase + mi * 16 + gr;
                float psA = 0.f, pdA = 0.f, psB = 0.f, pdB = 0.f;
#pragma unroll
                for (int ni = 0; ni < 4; ni++) {
                    const int gcol = nbase + ni * 8 + qc;
                    float* cc = c[mi][ni];
                    *(__half2*)&H[(size_t)row0 * HID + gcol] =
                        __floats2half2_rn(cc[0], cc[1]);
                    *(__half2*)&H[(size_t)(row0 + 8) * HID + gcol] =
                        __floats2half2_rn(cc[2], cc[3]);
                    psA = fmaf(cc[0], scr[gcol], fmaf(cc[1], scr[gcol + 1], psA));
                    pdA = fmaf(cc[0], scr[128 + gcol], fmaf(cc[1], scr[128 + gcol + 1], pdA));
                    psB = fmaf(cc[2], scr[gcol], fmaf(cc[3], scr[gcol + 1], psB));
                    pdB = fmaf(cc[2], scr[128 + gcol], fmaf(cc[3], scr[128 + gcol + 1], pdB));
                }
                psA += __shfl_xor_sync(FULLM, psA, 1); psA += __shfl_xor_sync(FULLM, psA, 2);
                pdA += __shfl_xor_sync(FULLM, pdA, 1); pdA += __shfl_xor_sync(FULLM, pdA, 2);
                psB += __shfl_xor_sync(FULLM, psB, 1); psB += __shfl_xor_sync(FULLM, psB, 2);
                pdB += __shfl_xor_sync(FULLM, pdB, 1); pdB += __shfl_xor_sync(FULLM, pdB, 2);
                if ((lane & 3) == 0) {
                    ALS[(size_t)row0 * HEADS + head] = psA;
                    ALD[(size_t)row0 * HEADS + head] = pdA;
                    ALS[(size_t)(row0 + 8) * HEADS + head] = psB;
                    ALD[(size_t)(row0 + 8) * HEADS + head] = pdB;
                }
            }
        } else {
            constexpr int PT = 132;
            float* T = (float*)smem;
#pragma unroll
            for (int mi = 0; mi < 4; mi++) {
                const int rl = mbase + mi * 16 + gr;
#pragma unroll
                for (int ni = 0; ni < 4; ni++) {
                    const int gcol = nbase + ni * 8 + qc;
                    float* cc = c[mi][ni];
                    float t0 = tanh_fast(cc[0] + scr[gcol]);
                    float t1 = tanh_fast(cc[1] + scr[gcol + 1]);
                    float t2 = tanh_fast(cc[2] + scr[gcol]);
                    float t3 = tanh_fast(cc[3] + scr[gcol + 1]);
                    *(float2*)&T[rl * PT + gcol] = make_float2(t0, t1);
                    *(float2*)&T[(rl + 8) * PT + gcol] = make_float2(t2, t3);
                }
            }
            __syncthreads();
            {
                const int row  = t >> 1;
                const int half = t & 1;
                float acc[8];
#pragma unroll
                for (int o = 0; o < 8; o++) acc[o] = 0.f;
                const float* Tr = T + row * PT + half * 64;
                const float* W2s = scr + 128;
#pragma unroll 4
                for (int k = 0; k < 64; k++) {
                    float tv = Tr[k];
                    const float* w = W2s + (half * 64 + k) * 8;
                    float4 wa = *(const float4*)w;
                    float4 wb = *(const float4*)(w + 4);
                    acc[0] = fmaf(tv, wa.x, acc[0]); acc[1] = fmaf(tv, wa.y, acc[1]);
                    acc[2] = fmaf(tv, wa.z, acc[2]); acc[3] = fmaf(tv, wa.w, acc[3]);
                    acc[4] = fmaf(tv, wb.x, acc[4]); acc[5] = fmaf(tv, wb.y, acc[5]);
                    acc[6] = fmaf(tv, wb.z, acc[6]); acc[7] = fmaf(tv, wb.w, acc[7]);
                }
#pragma unroll
                for (int o = 0; o < 8; o++) acc[o] += __shfl_xor_sync(FULLM, acc[o], 1);
                if (half == 0) {
                    float4 oa = make_float4(acc[0] + bm2[0], acc[1] + bm2[1],
                                            acc[2] + bm2[2], acc[3] + bm2[3]);
                    float4 ob = make_float4(acc[4] + bm2[4], acc[5] + bm2[5],
                                            acc[6] + bm2[6], acc[7] + bm2[7]);
                    *(float4*)&OUT[(size_t)(r0 + row) * DOUT + 0] = oa;
                    *(float4*)&OUT[(size_t)(r0 + row) * DOUT + 4] = ob;
                }
            }
        }
        __syncthreads();
    }
}

// =====================================================================
// GAT aggregate v3 (measured win): smem-parked alphas, zero-shuffle d-loop.
// =====================================================================
__global__ __launch_bounds__(256) void gat_aggregate(
    const __half* __restrict__ H, const float* __restrict__ ALS,
    const float* __restrict__ ALD,
    const float* __restrict__ bias, float* __restrict__ Xout)
{
    __shared__ int   s_idx[8][64];
    __shared__ float s_alp[8][64 * 4];

    const int warp = threadIdx.x >> 5;
    const int j    = (blockIdx.x * blockDim.x + threadIdx.x) >> 5;
    const int lane = threadIdx.x & 31;
    const int base = (j >> 8) << 8;

    const int d = g_rdeg[j];
    const uint8_t* adj = g_adj8 + (size_t)j * CAP;
    int n0 = (lane < d)      ? base + (int)adj[lane]      : -1;
    int n1 = (lane + 32 < d) ? base + (int)adj[lane + 32] : -1;

    const float4 aldj = *(const float4*)&ALD[(size_t)j * HEADS];

    float e00 = -3.0e38f, e01 = -3.0e38f, e02 = -3.0e38f, e03 = -3.0e38f;
    float e10 = -3.0e38f, e11 = -3.0e38f, e12 = -3.0e38f, e13 = -3.0e38f;
    if (n0 >= 0) {
        float4 s = *(const float4*)&ALS[(size_t)n0 * HEADS];
        e00 = lrelu(s.x + aldj.x); e01 = lrelu(s.y + aldj.y);
        e02 = lrelu(s.z + aldj.z); e03 = lrelu(s.w + aldj.w);
    }
    if (n1 >= 0) {
        float4 s = *(const float4*)&ALS[(size_t)n1 * HEADS];
        e10 = lrelu(s.x + aldj.x); e11 = lrelu(s.y + aldj.y);
        e12 = lrelu(s.z + aldj.z); e13 = lrelu(s.w + aldj.w);
    }

    float a00, a01, a02, a03, a10, a11, a12, a13;
#define SOFTMAX_HEAD(E0, E1, A0, A1)                                        \
    {                                                                       \
        float m = fmaxf(E0, E1);                                            \
        for (int o = 16; o; o >>= 1) m = fmaxf(m, __shfl_xor_sync(FULLM, m, o)); \
        float p0 = (n0 >= 0) ? __expf(E0 - m) : 0.f;                        \
        float p1 = (n1 >= 0) ? __expf(E1 - m) : 0.f;                        \
        float s = p0 + p1;                                                  \
        for (int o = 16; o; o >>= 1) s += __shfl_xor_sync(FULLM, s, o);     \
        float inv = 1.f / (s + 1e-16f);                                     \
        A0 = p0 * inv; A1 = p1 * inv;                                       \
    }
    SOFTMAX_HEAD(e00, e10, a00, a10)
    SOFTMAX_HEAD(e01, e11, a01, a11)
    SOFTMAX_HEAD(e02, e12, a02, a12)
    SOFTMAX_HEAD(e03, e13, a03, a13)
#undef SOFTMAX_HEAD

    s_idx[warp][lane]      = n0;
    s_idx[warp][lane + 32] = n1;
    *(float4*)&s_alp[warp][lane * 4]        = make_float4(a00, a01, a02, a03);
    *(float4*)&s_alp[warp][(lane + 32) * 4] = make_float4(a10, a11, a12, a13);
    __syncwarp();

    const int hsel = lane >> 3;
    const int coff = lane * 4;
    float ax = 0.f, ay = 0.f, az = 0.f, aw = 0.f;
    for (int e = 0; e < d; e++) {
        int   i = s_idx[warp][e];
        float w = s_alp[warp][e * 4 + hsel];
        uint2 hv = *(const uint2*)&H[(size_t)i * HID + coff];
        float2 f0 = __half22float2(*(__half2*)&hv.x);
        float2 f1 = __half22float2(*(__half2*)&hv.y);
        ax = fmaf(w, f0.x, ax);
        ay = fmaf(w, f0.y, ay);
        az = fmaf(w, f1.x, az);
        aw = fmaf(w, f1.y, aw);
    }

    float4 bv = *(const float4*)&bias[coff];
    float4 o = make_float4(fmaxf(ax + bv.x, 0.f), fmaxf(ay + bv.y, 0.f),
                           fmaxf(az + bv.z, 0.f), fmaxf(aw + bv.w, 0.f));
    *(float4*)&Xout[(size_t)j * HID + coff] = o;
}

// =====================================================================
// Launcher
// =====================================================================
extern "C" void kernel_launch(void* const* d_in, const int* in_sizes, int n_in,
                              void* d_out, int out_size)
{
    const float* obs    = (const float*)d_in[0];
    const float* W1     = (const float*)d_in[1];
    const float* a1_src = (const float*)d_in[2];
    const float* a1_dst = (const float*)d_in[3];
    const float* b1     = (const float*)d_in[4];
    const float* W2     = (const float*)d_in[5];
    const float* a2_src = (const float*)d_in[6];
    const float* a2_dst = (const float*)d_in[7];
    const float* b2     = (const float*)d_in[8];
    const float* Wm1    = (const float*)d_in[9];
    const float* bm1    = (const float*)d_in[10];
    const float* Wm2    = (const float*)d_in[11];
    const float* bm2    = (const float*)d_in[12];
    float* out = (float*)d_out;

    __half* hbuf; cudaGetSymbolAddress((void**)&hbuf, g_hbuf);
    float* xbuf; cudaGetSymbolAddress((void**)&xbuf, g_xbuf);
    float* als;  cudaGetSymbolAddress((void**)&als,  g_als);
    float* ald;  cudaGetSymbolAddress((void**)&ald,  g_ald);
    __nv_bfloat16 *w1h, *w1l, *w2h, *w2l, *wm1h, *wm1l;
    cudaGetSymbolAddress((void**)&w1h,  g_w1_hi);
    cudaGetSymbolAddress((void**)&w1l,  g_w1_lo);
    cudaGetSymbolAddress((void**)&w2h,  g_w2_hi);
    cudaGetSymbolAddress((void**)&w2l,  g_w2_lo);
    cudaGetSymbolAddress((void**)&wm1h, g_wm1_hi);
    cudaGetSymbolAddress((void**)&wm1l, g_wm1_lo);

    const int SMEM32  = 3 * 128 * (DIN + 8) * 2 + 4608;    //  35,328 B
    const int SMEM128 = 3 * 128 * (HID + 8) * 2 + 4608;    // 109,056 B
    cudaFuncSetAttribute(mma_gemm<DIN, 0>, cudaFuncAttributeMaxDynamicSharedMemorySize, SMEM32);
    cudaFuncSetAttribute(mma_gemm<HID, 0>, cudaFuncAttributeMaxDynamicSharedMemorySize, SMEM128);
    cudaFuncSetAttribute(mma_gemm<HID, 1>, cudaFuncAttributeMaxDynamicSharedMemorySize, SMEM128);
    cudaFuncSetAttribute(knn_kernel, cudaFuncAttributeMaxDynamicSharedMemorySize, KNN_SMEM);

    const int NSM      = 148;
    const int GRID32   = 2 * NSM;
    const int GRID128  = 2 * NSM;
    const int AGG_BLOCKS = NODES / 8;

    prep_w_kernel<<<(DIN * 128 + 255) / 256, 256>>>(W1,  DIN, w1h,  w1l);
    prep_w_kernel<<<(HID * 128 + 255) / 256, 256>>>(W2,  HID, w2h,  w2l);
    prep_w_kernel<<<(HID * 128 + 255) / 256, 256>>>(Wm1, HID, wm1h, wm1l);

    knn_kernel<<<Bsz, 1024, KNN_SMEM>>>(obs);

    mma_gemm<DIN, 0><<<GRID32, 256, SMEM32>>>(obs, w1h, w1l, a1_src, a1_dst,
        nullptr, nullptr, nullptr, hbuf, als, ald, nullptr);
    gat_aggregate<<<AGG_BLOCKS, 256>>>(hbuf, als, ald, b1, xbuf);

    mma_gemm<HID, 0><<<GRID128, 256, SMEM128>>>(xbuf, w2h, w2l, a2_src, a2_dst,
        nullptr, nullptr, nullptr, hbuf, als, ald, nullptr);
    gat_aggregate<<<AGG_BLOCKS, 256>>>(hbuf, als, ald, b2, xbuf);

    mma_gemm<HID, 1><<<GRID128, 256, SMEM128>>>(xbuf, wm1h, wm1l, nullptr, nullptr,
        bm1, Wm2, bm2, nullptr, nullptr, nullptr, out);
}

// round 17
// speedup vs baseline: 1.0009x; 1.0009x over previous
#include <cuda_runtime.h>
#include <cuda_bf16.h>
#include <cuda_fp16.h>
#include <cstdint>
#include <math.h>

#define Bsz   512
#define Nn    256
#define NODES (Bsz * Nn)      // 131072
#define DIN   32
#define HID   128
#define HEADS 4
#define Knn   5
#define DOUT  8
#define CAP   40
#define NEG_SLOPE 0.2f
#define FULLM 0xffffffffu
#define NTILES (NODES / 128)  // 1024

// ---------------- static device scratch ----------------
__device__ int     g_rdeg[NODES];
__device__ uint8_t g_adj8[(size_t)NODES * CAP];
__device__ __half  g_hbuf[(size_t)NODES * HID];
__device__ float   g_xbuf[(size_t)NODES * HID];
__device__ float   g_als[(size_t)NODES * HEADS];
__device__ float   g_ald[(size_t)NODES * HEADS];
__device__ __nv_bfloat16 g_w1_hi[128 * DIN],  g_w1_lo[128 * DIN];
__device__ __nv_bfloat16 g_w2_hi[128 * HID],  g_w2_lo[128 * HID];
__device__ __nv_bfloat16 g_wm1_hi[128 * HID], g_wm1_lo[128 * HID];

__device__ __forceinline__ float tanh_fast(float x) {
    return __fdividef(2.f, 1.f + __expf(-2.f * x)) - 1.f;
}
__device__ __forceinline__ float lrelu(float v) {
    return (v > 0.f) ? v : NEG_SLOPE * v;
}
__device__ __forceinline__ uint32_t smem_u32(const void* p) {
    uint32_t a;
    asm("{ .reg .u64 t; cvta.to.shared.u64 t, %1; cvt.u32.u64 %0, t; }" : "=r"(a) : "l"(p));
    return a;
}
__device__ __forceinline__ void ldsm_x4(uint32_t* r, uint32_t addr) {
    asm volatile("ldmatrix.sync.aligned.m8n8.x4.shared.b16 {%0,%1,%2,%3}, [%4];"
                 : "=r"(r[0]), "=r"(r[1]), "=r"(r[2]), "=r"(r[3]) : "r"(addr));
}
__device__ __forceinline__ void ldsm_x2(uint32_t* r, uint32_t addr) {
    asm volatile("ldmatrix.sync.aligned.m8n8.x2.shared.b16 {%0,%1}, [%2];"
                 : "=r"(r[0]), "=r"(r[1]) : "r"(addr));
}
__device__ __forceinline__ void mma_bf16(float* c, const uint32_t* a, const uint32_t* b) {
    asm volatile("mma.sync.aligned.m16n8k16.row.col.f32.bf16.bf16.f32 "
                 "{%0,%1,%2,%3}, {%4,%5,%6,%7}, {%8,%9}, {%0,%1,%2,%3};"
                 : "+f"(c[0]), "+f"(c[1]), "+f"(c[2]), "+f"(c[3])
                 : "r"(a[0]), "r"(a[1]), "r"(a[2]), "r"(a[3]), "r"(b[0]), "r"(b[1]));
}
__device__ __forceinline__ uint32_t pack_bf2(__nv_bfloat16 a, __nv_bfloat16 b) {
    return (uint32_t)__bfloat16_as_ushort(a) | ((uint32_t)__bfloat16_as_ushort(b) << 16);
}

// =====================================================================
// Prep: W [K,128] -> hi/lo bf16 images of W^T [128][K]
// =====================================================================
__global__ void prep_w_kernel(const float* __restrict__ W, int K,
                              __nv_bfloat16* __restrict__ hi, __nv_bfloat16* __restrict__ lo)
{
    int idx = blockIdx.x * blockDim.x + threadIdx.x;
    if (idx >= K * 128) return;
    int k = idx >> 7, n = idx & 127;
    float x = W[idx];
    __nv_bfloat16 h = __float2bfloat16(x);
    __nv_bfloat16 l = __float2bfloat16(x - __bfloat162float(h));
    hi[n * K + k] = h;
    lo[n * K + k] = l;
}

// =====================================================================
// KNN (round-14 version, measured 55.5 us): 512 threads, 2 threads/node.
// =====================================================================
__global__ __launch_bounds__(512) void knn_kernel(const float* __restrict__ obs)
{
    __shared__ float2  sxy[Nn];
    __shared__ int     sdeg[Nn];
    __shared__ uint8_t sadj[Nn * CAP];
    __shared__ float   mbd[Nn * 2 * Knn];
    __shared__ int     mbi[Nn * 2 * Knn];

    const int b = blockIdx.x;
    const int t = threadIdx.x;
    const int n = t & (Nn - 1);
    const int half = t >> 8;

    if (t < Nn) {
        const size_t base = ((size_t)b * Nn + n) * DIN;
        sxy[n] = make_float2(obs[base + 0], obs[base + 1]);
        sdeg[n] = 1;
        sadj[n * CAP + 0] = (uint8_t)n;
    }
    __syncthreads();

    const float2 p = sxy[n];
    float bd[Knn];
    int   bi[Knn];
#pragma unroll
    for (int s = 0; s < Knn; s++) { bd[s] = 3.0e38f; bi[s] = -1; }

    const int j0 = half * 128;
    for (int jj = 0; jj < 128; jj++) {
        const int j = j0 + jj;
        float2 c = sxy[j];
        float dx = c.x - p.x;
        float dy = c.y - p.y;
        float d  = fmaf(dx, dx, dy * dy);
        if (j == n) d = 3.0e38f;
        if (d < bd[Knn - 1]) {
            bd[Knn - 1] = d; bi[Knn - 1] = j;
#pragma unroll
            for (int s = Knn - 2; s >= 0; s--) {
                if (bd[s + 1] < bd[s]) {
                    float td = bd[s]; bd[s] = bd[s + 1]; bd[s + 1] = td;
                    int   ti = bi[s]; bi[s] = bi[s + 1]; bi[s + 1] = ti;
                }
            }
        }
    }
#pragma unroll
    for (int s = 0; s < Knn; s++) {
        mbd[(n * 2 + half) * Knn + s] = bd[s];
        mbi[(n * 2 + half) * Knn + s] = bi[s];
    }
    __syncthreads();

    if (t < Nn) {
        const float* A  = &mbd[(n * 2 + 0) * Knn];
        const float* B  = &mbd[(n * 2 + 1) * Knn];
        const int*   Ai = &mbi[(n * 2 + 0) * Knn];
        const int*   Bi = &mbi[(n * 2 + 1) * Knn];
        int ia = 0, ib = 0;
#pragma unroll
        for (int s = 0; s < Knn; s++) {
            int jn;
            if (A[ia] <= B[ib]) jn = Ai[ia++];
            else                jn = Bi[ib++];
            int p2 = atomicAdd(&sdeg[jn], 1);
            if (p2 < CAP) sadj[jn * CAP + p2] = (uint8_t)n;
        }
    }
    __syncthreads();

    if (t < Nn) {
        int deg = min(sdeg[n], CAP);
        g_rdeg[b * Nn + n] = deg;
        uint8_t* dst = g_adj8 + (size_t)(b * Nn + n) * CAP;
        const uint32_t* srcw = (const uint32_t*)&sadj[n * CAP];
#pragma unroll
        for (int w = 0; w < CAP / 4; w++)
            ((uint32_t*)dst)[w] = srcw[w];
    }
}

// =====================================================================
// PERSISTENT mma.sync GEMM. FOURTILE=1 (K=32): sBhi+sBlo resident, no swap.
// Otherwise 3-tile with B swap (2 CTAs/SM).
// =====================================================================
template<int KDIM, int MODE, int FOURTILE>
__global__ __launch_bounds__(256, 2) void mma_gemm(
    const float* __restrict__ X,
    const __nv_bfloat16* __restrict__ gBhi, const __nv_bfloat16* __restrict__ gBlo,
    const float* __restrict__ asrc, const float* __restrict__ adst,
    const float* __restrict__ bias, const float* __restrict__ Wm2,
    const float* __restrict__ bm2,
    __half* __restrict__ H, float* __restrict__ ALS, float* __restrict__ ALD,
    float* __restrict__ OUT)
{
    constexpr int PK = KDIM + 8;
    extern __shared__ __align__(16) char smem[];
    __nv_bfloat16* sAhi = (__nv_bfloat16*)smem;
    __nv_bfloat16* sAlo = sAhi + 128 * PK;
    __nv_bfloat16* sB   = sAlo + 128 * PK;          // 3-tile: shared B
    __nv_bfloat16* sB2  = sB + (FOURTILE ? 128 * PK : 0);  // 4-tile: Blo
    float* scr = (float*)(sB + (FOURTILE ? 2 : 1) * 128 * PK);

    const int t = threadIdx.x, wid = t >> 5, lane = t & 31;

    if (MODE == 0) {
        if (t < 128) { scr[t] = asrc[t]; scr[128 + t] = adst[t]; }
    } else {
        if (t < 128) scr[t] = bias[t];
        for (int e = t; e < 1024; e += 256) scr[128 + e] = Wm2[e];
    }
    if (FOURTILE) {   // B images loaded once (persistent)
        for (int idx = t; idx < 128 * (KDIM / 8); idx += 256) {
            int n  = idx / (KDIM / 8);
            int kc = (idx % (KDIM / 8)) * 8;
            *(float4*)&sB[n * PK + kc]  = *(const float4*)&gBhi[n * KDIM + kc];
            *(float4*)&sB2[n * PK + kc] = *(const float4*)&gBlo[n * KDIM + kc];
        }
    }
    __syncthreads();

    const int mbase = (wid & 1) * 64;
    const int nbase = (wid >> 1) * 32;
    const int arow = mbase + (lane & 7) + ((lane >> 3) & 1) * 8;
    const int ak   = (lane >> 4) * 8;
    const int brow = nbase + (lane & 7);
    const int bk   = ((lane >> 3) & 1) * 8;
    const int gr = lane >> 2;
    const int qc = (lane & 3) * 2;

    for (int tile = blockIdx.x; tile < NTILES; tile += gridDim.x) {
        const int r0 = tile * 128;

        for (int idx = t; idx < 128 * (KDIM / 2); idx += 256) {
            int row = idx / (KDIM / 2);
            int k   = (idx % (KDIM / 2)) * 2;
            float2 v = *(const float2*)&X[(size_t)(r0 + row) * KDIM + k];
            __nv_bfloat16 h0 = __float2bfloat16(v.x);
            __nv_bfloat16 h1 = __float2bfloat16(v.y);
            __nv_bfloat16 l0 = __float2bfloat16(v.x - __bfloat162float(h0));
            __nv_bfloat16 l1 = __float2bfloat16(v.y - __bfloat162float(h1));
            *(uint32_t*)&sAhi[row * PK + k] = pack_bf2(h0, h1);
            *(uint32_t*)&sAlo[row * PK + k] = pack_bf2(l0, l1);
        }
        if (!FOURTILE) {
            for (int idx = t; idx < 128 * (KDIM / 8); idx += 256) {
                int n  = idx / (KDIM / 8);
                int kc = (idx % (KDIM / 8)) * 8;
                *(float4*)&sB[n * PK + kc] = *(const float4*)&gBhi[n * KDIM + kc];
            }
        }
        __syncthreads();

        float c[4][4][4];
#pragma unroll
        for (int mi = 0; mi < 4; mi++)
#pragma unroll
            for (int ni = 0; ni < 4; ni++)
#pragma unroll
                for (int q = 0; q < 4; q++) c[mi][ni][q] = 0.f;

        // passes 1 & 2: Ah*Bh, Al*Bh
#pragma unroll
        for (int p = 0; p < 2; p++) {
            const __nv_bfloat16* A = (p == 1) ? sAlo : sAhi;
#pragma unroll
            for (int ks = 0; ks < KDIM / 16; ks++) {
                uint32_t a[4][4], b[4][2];
#pragma unroll
                for (int mi = 0; mi < 4; mi++)
                    ldsm_x4(a[mi], smem_u32(&A[(arow + mi * 16) * PK + ks * 16 + ak]));
#pragma unroll
                for (int ni = 0; ni < 4; ni++)
                    ldsm_x2(b[ni], smem_u32(&sB[(brow + ni * 8) * PK + ks * 16 + bk]));
#pragma unroll
                for (int mi = 0; mi < 4; mi++)
#pragma unroll
                    for (int ni = 0; ni < 4; ni++)
                        mma_bf16(c[mi][ni], a[mi], b[ni]);
            }
        }
        const __nv_bfloat16* Bl;
        if (FOURTILE) {
            Bl = sB2;
        } else {
            __syncthreads();
            for (int idx = t; idx < 128 * (KDIM / 8); idx += 256) {
                int n  = idx / (KDIM / 8);
                int kc = (idx % (KDIM / 8)) * 8;
                *(float4*)&sB[n * PK + kc] = *(const float4*)&gBlo[n * KDIM + kc];
            }
            __syncthreads();
            Bl = sB;
        }
        // pass 3: Ah*Bl
#pragma unroll
        for (int ks = 0; ks < KDIM / 16; ks++) {
            uint32_t a[4][4], b[4][2];
#pragma unroll
            for (int mi = 0; mi < 4; mi++)
                ldsm_x4(a[mi], smem_u32(&sAhi[(arow + mi * 16) * PK + ks * 16 + ak]));
#pragma unroll
            for (int ni = 0; ni < 4; ni++)
                ldsm_x2(b[ni], smem_u32(&Bl[(brow + ni * 8) * PK + ks * 16 + bk]));
#pragma unroll
            for (int mi = 0; mi < 4; mi++)
#pragma unroll
                for (int ni = 0; ni < 4; ni++)
                    mma_bf16(c[mi][ni], a[mi], b[ni]);
        }
        __syncthreads();

        if (MODE == 0) {
            const int head = wid >> 1;
#pragma unroll
            for (int mi = 0; mi < 4; mi++) {
                const int row0 = r0 + mbase + mi * 16 + gr;
                float psA = 0.f, pdA = 0.f, psB = 0.f, pdB = 0.f;
#pragma unroll
                for (int ni = 0; ni < 4; ni++) {
                    const int gcol = nbase + ni * 8 + qc;
                    float* cc = c[mi][ni];
                    *(__half2*)&H[(size_t)row0 * HID + gcol] =
                        __floats2half2_rn(cc[0], cc[1]);
                    *(__half2*)&H[(size_t)(row0 + 8) * HID + gcol] =
                        __floats2half2_rn(cc[2], cc[3]);
                    psA = fmaf(cc[0], scr[gcol], fmaf(cc[1], scr[gcol + 1], psA));
                    pdA = fmaf(cc[0], scr[128 + gcol], fmaf(cc[1], scr[128 + gcol + 1], pdA));
                    psB = fmaf(cc[2], scr[gcol], fmaf(cc[3], scr[gcol + 1], psB));
                    pdB = fmaf(cc[2], scr[128 + gcol], fmaf(cc[3], scr[128 + gcol + 1], pdB));
                }
                psA += __shfl_xor_sync(FULLM, psA, 1); psA += __shfl_xor_sync(FULLM, psA, 2);
                pdA += __shfl_xor_sync(FULLM, pdA, 1); pdA += __shfl_xor_sync(FULLM, pdA, 2);
                psB += __shfl_xor_sync(FULLM, psB, 1); psB += __shfl_xor_sync(FULLM, psB, 2);
                pdB += __shfl_xor_sync(FULLM, pdB, 1); pdB += __shfl_xor_sync(FULLM, pdB, 2);
                if ((lane & 3) == 0) {
                    ALS[(size_t)row0 * HEADS + head] = psA;
                    ALD[(size_t)row0 * HEADS + head] = pdA;
                    ALS[(size_t)(row0 + 8) * HEADS + head] = psB;
                    ALD[(size_t)(row0 + 8) * HEADS + head] = pdB;
                }
            }
        } else {
            constexpr int PT = 132;
            float* T = (float*)smem;
#pragma unroll
            for (int mi = 0; mi < 4; mi++) {
                const int rl = mbase + mi * 16 + gr;
#pragma unroll
                for (int ni = 0; ni < 4; ni++) {
                    const int gcol = nbase + ni * 8 + qc;
                    float* cc = c[mi][ni];
                    float t0 = tanh_fast(cc[0] + scr[gcol]);
                    float t1 = tanh_fast(cc[1] + scr[gcol + 1]);
                    float t2 = tanh_fast(cc[2] + scr[gcol]);
                    float t3 = tanh_fast(cc[3] + scr[gcol + 1]);
                    *(float2*)&T[rl * PT + gcol] = make_float2(t0, t1);
                    *(float2*)&T[(rl + 8) * PT + gcol] = make_float2(t2, t3);
                }
            }
            __syncthreads();
            {
                const int row  = t >> 1;
                const int half = t & 1;
                float acc[8];
#pragma unroll
                for (int o = 0; o < 8; o++) acc[o] = 0.f;
                const float* Tr = T + row * PT + half * 64;
                const float* W2s = scr + 128;
#pragma unroll 4
                for (int k = 0; k < 64; k++) {
                    float tv = Tr[k];
                    const float* w = W2s + (half * 64 + k) * 8;
                    float4 wa = *(const float4*)w;
                    float4 wb = *(const float4*)(w + 4);
                    acc[0] = fmaf(tv, wa.x, acc[0]); acc[1] = fmaf(tv, wa.y, acc[1]);
                    acc[2] = fmaf(tv, wa.z, acc[2]); acc[3] = fmaf(tv, wa.w, acc[3]);
                    acc[4] = fmaf(tv, wb.x, acc[4]); acc[5] = fmaf(tv, wb.y, acc[5]);
                    acc[6] = fmaf(tv, wb.z, acc[6]); acc[7] = fmaf(tv, wb.w, acc[7]);
                }
#pragma unroll
                for (int o = 0; o < 8; o++) acc[o] += __shfl_xor_sync(FULLM, acc[o], 1);
                if (half == 0) {
                    float4 oa = make_float4(acc[0] + bm2[0], acc[1] + bm2[1],
                                            acc[2] + bm2[2], acc[3] + bm2[3]);
                    float4 ob = make_float4(acc[4] + bm2[4], acc[5] + bm2[5],
                                            acc[6] + bm2[6], acc[7] + bm2[7]);
                    *(float4*)&OUT[(size_t)(r0 + row) * DOUT + 0] = oa;
                    *(float4*)&OUT[(size_t)(r0 + row) * DOUT + 4] = ob;
                }
            }
        }
        __syncthreads();
    }
}

// =====================================================================
// GAT aggregate: smem-parked alphas; d-loop 2-edge unrolled, dual accs.
// =====================================================================
__global__ __launch_bounds__(256) void gat_aggregate(
    const __half* __restrict__ H, const float* __restrict__ ALS,
    const float* __restrict__ ALD,
    const float* __restrict__ bias, float* __restrict__ Xout)
{
    __shared__ int   s_idx[8][64];
    __shared__ float s_alp[8][64 * 4];

    const int warp = threadIdx.x >> 5;
    const int j    = (blockIdx.x * blockDim.x + threadIdx.x) >> 5;
    const int lane = threadIdx.x & 31;
    const int base = (j >> 8) << 8;

    const int d = g_rdeg[j];
    const uint8_t* adj = g_adj8 + (size_t)j * CAP;
    int n0 = (lane < d)      ? base + (int)adj[lane]      : -1;
    int n1 = (lane + 32 < d) ? base + (int)adj[lane + 32] : -1;

    const float4 aldj = *(const float4*)&ALD[(size_t)j * HEADS];

    float e00 = -3.0e38f, e01 = -3.0e38f, e02 = -3.0e38f, e03 = -3.0e38f;
    float e10 = -3.0e38f, e11 = -3.0e38f, e12 = -3.0e38f, e13 = -3.0e38f;
    if (n0 >= 0) {
        float4 s = *(const float4*)&ALS[(size_t)n0 * HEADS];
        e00 = lrelu(s.x + aldj.x); e01 = lrelu(s.y + aldj.y);
        e02 = lrelu(s.z + aldj.z); e03 = lrelu(s.w + aldj.w);
    }
    if (n1 >= 0) {
        float4 s = *(const float4*)&ALS[(size_t)n1 * HEADS];
        e10 = lrelu(s.x + aldj.x); e11 = lrelu(s.y + aldj.y);
        e12 = lrelu(s.z + aldj.z); e13 = lrelu(s.w + aldj.w);
    }

    float a00, a01, a02, a03, a10, a11, a12, a13;
#define SOFTMAX_HEAD(E0, E1, A0, A1)                                        \
    {                                                                       \
        float m = fmaxf(E0, E1);                                            \
        for (int o = 16; o; o >>= 1) m = fmaxf(m, __shfl_xor_sync(FULLM, m, o)); \
        float p0 = (n0 >= 0) ? __expf(E0 - m) : 0.f;                        \
        float p1 = (n1 >= 0) ? __expf(E1 - m) : 0.f;                        \
        float s = p0 + p1;                                                  \
        for (int o = 16; o; o >>= 1) s += __shfl_xor_sync(FULLM, s, o);     \
        float inv = 1.f / (s + 1e-16f);                                     \
        A0 = p0 * inv; A1 = p1 * inv;                                       \
    }
    SOFTMAX_HEAD(e00, e10, a00, a10)
    SOFTMAX_HEAD(e01, e11, a01, a11)
    SOFTMAX_HEAD(e02, e12, a02, a12)
    SOFTMAX_HEAD(e03, e13, a03, a13)
#undef SOFTMAX_HEAD

    s_idx[warp][lane]      = n0;
    s_idx[warp][lane + 32] = n1;
    *(float4*)&s_alp[warp][lane * 4]        = make_float4(a00, a01, a02, a03);
    *(float4*)&s_alp[warp][(lane + 32) * 4] = make_float4(a10, a11, a12, a13);
    __syncwarp();

    const int hsel = lane >> 3;
    const int coff = lane * 4;
    float ax0 = 0.f, ay0 = 0.f, az0 = 0.f, aw0 = 0.f;
    float ax1 = 0.f, ay1 = 0.f, az1 = 0.f, aw1 = 0.f;
    int e = 0;
    for (; e + 2 <= d; e += 2) {
        int   i0 = s_idx[warp][e];
        int   i1 = s_idx[warp][e + 1];
        float w0 = s_alp[warp][e * 4 + hsel];
        float w1 = s_alp[warp][(e + 1) * 4 + hsel];
        uint2 h0 = *(const uint2*)&H[(size_t)i0 * HID + coff];
        uint2 h1 = *(const uint2*)&H[(size_t)i1 * HID + coff];
        float2 f00 = __half22float2(*(__half2*)&h0.x);
        float2 f01 = __half22float2(*(__half2*)&h0.y);
        float2 f10 = __half22float2(*(__half2*)&h1.x);
        float2 f11 = __half22float2(*(__half2*)&h1.y);
        ax0 = fmaf(w0, f00.x, ax0); ay0 = fmaf(w0, f00.y, ay0);
        az0 = fmaf(w0, f01.x, az0); aw0 = fmaf(w0, f01.y, aw0);
        ax1 = fmaf(w1, f10.x, ax1); ay1 = fmaf(w1, f10.y, ay1);
        az1 = fmaf(w1, f11.x, az1); aw1 = fmaf(w1, f11.y, aw1);
    }
    if (e < d) {
        int   i0 = s_idx[warp][e];
        float w0 = s_alp[warp][e * 4 + hsel];
        uint2 h0 = *(const uint2*)&H[(size_t)i0 * HID + coff];
        float2 f00 = __half22float2(*(__half2*)&h0.x);
        float2 f01 = __half22float2(*(__half2*)&h0.y);
        ax0 = fmaf(w0, f00.x, ax0); ay0 = fmaf(w0, f00.y, ay0);
        az0 = fmaf(w0, f01.x, az0); aw0 = fmaf(w0, f01.y, aw0);
    }
    float ax = ax0 + ax1, ay = ay0 + ay1, az = az0 + az1, aw = aw0 + aw1;

    float4 bv = *(const float4*)&bias[coff];
    float4 o = make_float4(fmaxf(ax + bv.x, 0.f), fmaxf(ay + bv.y, 0.f),
                           fmaxf(az + bv.z, 0.f), fmaxf(aw + bv.w, 0.f));
    *(float4*)&Xout[(size_t)j * HID + coff] = o;
}

// =====================================================================
// Launcher
// =====================================================================
extern "C" void kernel_launch(void* const* d_in, const int* in_sizes, int n_in,
                              void* d_out, int out_size)
{
    const float* obs    = (const float*)d_in[0];
    const float* W1     = (const float*)d_in[1];
    const float* a1_src = (const float*)d_in[2];
    const float* a1_dst = (const float*)d_in[3];
    const float* b1     = (const float*)d_in[4];
    const float* W2     = (const float*)d_in[5];
    const float* a2_src = (const float*)d_in[6];
    const float* a2_dst = (const float*)d_in[7];
    const float* b2     = (const float*)d_in[8];
    const float* Wm1    = (const float*)d_in[9];
    const float* bm1    = (const float*)d_in[10];
    const float* Wm2    = (const float*)d_in[11];
    const float* bm2    = (const float*)d_in[12];
    float* out = (float*)d_out;

    __half* hbuf; cudaGetSymbolAddress((void**)&hbuf, g_hbuf);
    float* xbuf; cudaGetSymbolAddress((void**)&xbuf, g_xbuf);
    float* als;  cudaGetSymbolAddress((void**)&als,  g_als);
    float* ald;  cudaGetSymbolAddress((void**)&ald,  g_ald);
    __nv_bfloat16 *w1h, *w1l, *w2h, *w2l, *wm1h, *wm1l;
    cudaGetSymbolAddress((void**)&w1h,  g_w1_hi);
    cudaGetSymbolAddress((void**)&w1l,  g_w1_lo);
    cudaGetSymbolAddress((void**)&w2h,  g_w2_hi);
    cudaGetSymbolAddress((void**)&w2l,  g_w2_lo);
    cudaGetSymbolAddress((void**)&wm1h, g_wm1_hi);
    cudaGetSymbolAddress((void**)&wm1l, g_wm1_lo);

    const int SMEM32  = 4 * 128 * (DIN + 8) * 2 + 4608;    //  45,568 B (4-tile)
    const int SMEM128 = 3 * 128 * (HID + 8) * 2 + 4608;    // 109,056 B (3-tile)
    cudaFuncSetAttribute(mma_gemm<DIN, 0, 1>, cudaFuncAttributeMaxDynamicSharedMemorySize, SMEM32);
    cudaFuncSetAttribute(mma_gemm<HID, 0, 0>, cudaFuncAttributeMaxDynamicSharedMemorySize, SMEM128);
    cudaFuncSetAttribute(mma_gemm<HID, 1, 0>, cudaFuncAttributeMaxDynamicSharedMemorySize, SMEM128);

    const int NSM      = 148;
    const int GRID32   = 2 * NSM;
    const int GRID128  = 2 * NSM;
    const int AGG_BLOCKS = NODES / 8;

    prep_w_kernel<<<(DIN * 128 + 255) / 256, 256>>>(W1,  DIN, w1h,  w1l);
    prep_w_kernel<<<(HID * 128 + 255) / 256, 256>>>(W2,  HID, w2h,  w2l);
    prep_w_kernel<<<(HID * 128 + 255) / 256, 256>>>(Wm1, HID, wm1h, wm1l);

    knn_kernel<<<Bsz, 512>>>(obs);

    mma_gemm<DIN, 0, 1><<<GRID32, 256, SMEM32>>>(obs, w1h, w1l, a1_src, a1_dst,
        nullptr, nullptr, nullptr, hbuf, als, ald, nullptr);
    gat_aggregate<<<AGG_BLOCKS, 256>>>(hbuf, als, ald, b1, xbuf);

    mma_gemm<HID, 0, 0><<<GRID128, 256, SMEM128>>>(xbuf, w2h, w2l, a2_src, a2_dst,
        nullptr, nullptr, nullptr, hbuf, als, ald, nullptr);
    gat_aggregate<<<AGG_BLOCKS, 256>>>(hbuf, als, ald, b2, xbuf);

    mma_gemm<HID, 1, 0><<<GRID128, 256, SMEM128>>>(xbuf, wm1h, wm1l, nullptr, nullptr,
        bm1, Wm2, bm2, nullptr, nullptr, nullptr, out);
}